// round 14
// baseline (speedup 1.0000x reference)
#include <cuda_runtime.h>
#include <cuda_fp16.h>

#define SS   1024
#define BB   8
#define NH   8
#define BH   (BB * NH)          // 64

// Scratch: attention out, fp16, ROW-FEATURE layout [b*1024+s][h*8+d]  (1 MB)
__device__ __half g_aoh[BB * SS * 64];

// attn smem: kh[1024][8] half (16KB), vt[8][1032] half (16.5KB)
#define SM_KH 0
#define SM_VT 16384
#define VT_STRIDE 1032              // word-stride 516 = 4 mod 32: bank-free b-frags
#define SMEM_BYTES (16384 + 8 * VT_STRIDE * 2)   // 32896

__device__ __forceinline__ unsigned h2pk(float hi, float lo) {
    unsigned r; asm("cvt.rn.f16x2.f32 %0,%1,%2;" : "=r"(r) : "f"(hi), "f"(lo)); return r;
}
__device__ __forceinline__ unsigned ex2h2(unsigned x) {
    unsigned r; asm("ex2.approx.f16x2 %0,%1;" : "=r"(r) : "r"(x)); return r;
}
__device__ __forceinline__ unsigned hadd2(unsigned a, unsigned b) {
    unsigned r; asm("add.rn.f16x2 %0,%1,%2;" : "=r"(r) : "r"(a), "r"(b)); return r;
}
__device__ __forceinline__ float2 h2f2(unsigned v) {
    __half2 h = *(__half2*)&v;
    return __half22float2(h);
}
__device__ __forceinline__ void mma_16x8x8(float& c0, float& c1, float& c2, float& c3,
                                           unsigned a0, unsigned a1, unsigned b0) {
    asm("mma.sync.aligned.m16n8k8.row.col.f32.f16.f16.f32 "
        "{%0,%1,%2,%3},{%4,%5},{%6},{%0,%1,%2,%3};"
        : "+f"(c0), "+f"(c1), "+f"(c2), "+f"(c3)
        : "r"(a0), "r"(a1), "r"(b0));
}
__device__ __forceinline__ void mma_16x8x16(float& c0, float& c1, float& c2, float& c3,
                                            unsigned a0, unsigned a1, unsigned a2, unsigned a3,
                                            unsigned b0, unsigned b1) {
    asm("mma.sync.aligned.m16n8k16.row.col.f32.f16.f16.f32 "
        "{%0,%1,%2,%3},{%4,%5,%6,%7},{%8,%9},{%0,%1,%2,%3};"
        : "+f"(c0), "+f"(c1), "+f"(c2), "+f"(c3)
        : "r"(a0), "r"(a1), "r"(a2), "r"(a3), "r"(b0), "r"(b1));
}

// ---------------------------------------------------------------------------
// Fused qlayer + flash-attention via mma.sync.
// OCCUPANCY play: __launch_bounds__(256, 4) -> 64-reg target, 4 blocks/SM,
// 8 warps/SMSP, grid 512 = ONE wave. HMMA result latency (~800cy/iter) is
// covered by 2x the resident warps of all prior rounds.
// Grid 512 = 64 heads x 8 row-tiles; each warp owns 16 q-rows.
// ---------------------------------------------------------------------------
__global__ __launch_bounds__(256, 4) void attn_kernel(const float* __restrict__ x,
                                                      const float* __restrict__ phi) {
    extern __shared__ char dynsmem[];
    __half*  kh = (__half*)(dynsmem + SM_KH);       // [j][8] row-major fp16
    __half*  vt = (__half*)(dynsmem + SM_VT);       // [d][VT_STRIDE] fp16
    const unsigned* khw = (const unsigned*)kh;      // half2 words: [j*4 + p]
    const unsigned* vtw = (const unsigned*)vt;      // [d*516 + j/2]

    const int blk = blockIdx.x;
    const int bh = blk >> 3;
    const int b = bh >> 3, h = bh & 7;
    const int tid = threadIdx.x;

    float ph0 = phi[0], ph1 = phi[1], ph2 = phi[2], ph3 = phi[3];
    float ph4 = phi[4], ph5 = phi[5], ph6 = phi[6], ph7 = phi[7];

    // ---- prologue: qlayer (prefix products of cos) -> kh and vt ----
    #pragma unroll
    for (int it = 0; it < 4; it++) {
        int s = tid + it * 256;
        const float4* xp = (const float4*)(x + ((size_t)((b << 10) + s) << 6) + (h << 3));
        float4 xa = xp[0];
        float4 xb = xp[1];
        float k0 = __cosf(xa.x + ph0);
        float c1 = __cosf(xa.y + ph1);
        float c2 = __cosf(xa.z + ph2);
        float c3 = __cosf(xa.w + ph3);
        float c4 = __cosf(xb.x + ph4);
        float c5 = __cosf(xb.y + ph5);
        float c6 = __cosf(xb.z + ph6);
        float c7 = __cosf(xb.w + ph7);
        float kv1 = k0 * c1;
        float kv2 = kv1 * c2;
        float kv3 = kv2 * c3;
        float kv4 = kv3 * c4;
        float kv5 = kv4 * c5;
        float kv6 = kv5 * c6;
        float kv7 = kv6 * c7;
        float t = c1 * c2;
        t *= c3; t *= c4; t *= c5; t *= c6; t *= c7;

        unsigned w0 = h2pk(kv1, t);
        unsigned w1 = h2pk(kv3, kv2);
        unsigned w2 = h2pk(kv5, kv4);
        unsigned w3 = h2pk(kv7, kv6);
        ((uint4*)kh)[s] = make_uint4(w0, w1, w2, w3);

        __half2 p0 = *(__half2*)&w0, p1 = *(__half2*)&w1;
        __half2 p2 = *(__half2*)&w2, p3 = *(__half2*)&w3;
        vt[0 * VT_STRIDE + s] = p0.x;
        vt[1 * VT_STRIDE + s] = p0.y;
        vt[2 * VT_STRIDE + s] = p1.x;
        vt[3 * VT_STRIDE + s] = p1.y;
        vt[4 * VT_STRIDE + s] = p2.x;
        vt[5 * VT_STRIDE + s] = p2.y;
        vt[6 * VT_STRIDE + s] = p3.x;
        vt[7 * VT_STRIDE + s] = p3.y;
    }
    __syncthreads();

    // ---- per-warp Q fragments: q = fp16(k * log2e/sqrt8) ----
    const int wid = tid >> 5, lane = tid & 31;
    const int r0 = ((blk & 7) << 7) + (wid << 4);
    const int qr = lane >> 2, qm = lane & 3;
    const float SC = 0.35355339059327373f * 1.4426950408889634f;

    unsigned qh_a0, qh_a1;
    {
        float2 f0 = h2f2(khw[(r0 + qr) * 4 + qm]);
        qh_a0 = h2pk(f0.y * SC, f0.x * SC);
        float2 f1 = h2f2(khw[(r0 + qr + 8) * 4 + qm]);
        qh_a1 = h2pk(f1.y * SC, f1.x * SC);
    }

    // 2 independent O accumulator quads (keys 0-15 / 16-31 of each chunk)
    float oX0=0.f,oX1=0.f,oX2=0.f,oX3=0.f;
    float oY0=0.f,oY1=0.f,oY2=0.f,oY3=0.f;
    float l0 = 0.f, l1 = 0.f;

    const int vbase = (lane >> 2) * (VT_STRIDE / 2) + (lane & 3);

    for (int c = 0; c < SS; c += 32) {
        unsigned b0 = khw[(c +  0) * 4 + lane];
        unsigned b1 = khw[(c +  8) * 4 + lane];
        unsigned b2 = khw[(c + 16) * 4 + lane];
        unsigned b3 = khw[(c + 24) * 4 + lane];
        unsigned vb0 = vtw[vbase + (c >> 1)];
        unsigned vb1 = vtw[vbase + (c >> 1) + 4];
        unsigned vb2 = vtw[vbase + (c >> 1) + 8];
        unsigned vb3 = vtw[vbase + (c >> 1) + 12];

        float s00=0.f,s01=0.f,s02=0.f,s03=0.f;
        float s10=0.f,s11=0.f,s12=0.f,s13=0.f;
        float s20=0.f,s21=0.f,s22=0.f,s23=0.f;
        float s30=0.f,s31=0.f,s32=0.f,s33=0.f;
        mma_16x8x8(s00,s01,s02,s03, qh_a0,qh_a1, b0);
        mma_16x8x8(s10,s11,s12,s13, qh_a0,qh_a1, b1);
        mma_16x8x8(s20,s21,s22,s23, qh_a0,qh_a1, b2);
        mma_16x8x8(s30,s31,s32,s33, qh_a0,qh_a1, b3);

        unsigned a00 = ex2h2(h2pk(s01, s00));
        unsigned a01 = ex2h2(h2pk(s03, s02));
        unsigned a10 = ex2h2(h2pk(s11, s10));
        unsigned a11 = ex2h2(h2pk(s13, s12));
        unsigned a20 = ex2h2(h2pk(s21, s20));
        unsigned a21 = ex2h2(h2pk(s23, s22));
        unsigned a30 = ex2h2(h2pk(s31, s30));
        unsigned a31 = ex2h2(h2pk(s33, s32));

        unsigned T0 = hadd2(hadd2(a00, a10), hadd2(a20, a30));
        unsigned T1 = hadd2(hadd2(a01, a11), hadd2(a21, a31));
        float2 f0 = h2f2(T0);
        float2 f1 = h2f2(T1);
        l0 += f0.x + f0.y;
        l1 += f1.x + f1.y;

        mma_16x8x16(oX0,oX1,oX2,oX3, a00, a01, a10, a11, vb0, vb1);
        mma_16x8x16(oY0,oY1,oY2,oY3, a20, a21, a30, a31, vb2, vb3);
    }

    float o0 = oX0 + oY0, o1 = oX1 + oY1, o2 = oX2 + oY2, o3 = oX3 + oY3;

    l0 += __shfl_xor_sync(0xffffffffu, l0, 1);
    l0 += __shfl_xor_sync(0xffffffffu, l0, 2);
    l1 += __shfl_xor_sync(0xffffffffu, l1, 1);
    l1 += __shfl_xor_sync(0xffffffffu, l1, 2);
    float inv0 = 1.f / l0;
    float inv1 = 1.f / l1;

    // ---- write O as fp16: rows r0+qr(+8); feats h*8 + 2qm, +1 ----
    {
        unsigned* aoh = (unsigned*)g_aoh;
        int roww = (((b << 10) + r0 + qr) << 5) + (h << 2) + qm;
        aoh[roww]       = h2pk(o1 * inv0, o0 * inv0);
        aoh[roww + 256] = h2pk(o3 * inv1, o2 * inv1);   // +8 rows = +8*32 words
    }
}

// ---------------------------------------------------------------------------
// Tensor-core epilogue (unchanged from R12): out = ao @ W^T + bias.
// ---------------------------------------------------------------------------
__global__ __launch_bounds__(256) void epilogue_kernel(const float* __restrict__ W,
                                                       const float* __restrict__ bias,
                                                       float* __restrict__ out) {
    __shared__ __align__(16) __half sA[32 * 64];    // 4 KB

    const int tid = threadIdx.x;
    const int row0 = blockIdx.x * 32;

    {
        const uint4* src = (const uint4*)((const __half*)g_aoh + (size_t)row0 * 64);
        int off = tid * 16;
        int sw = off ^ (((off >> 7) & 7) << 4);
        *(uint4*)((char*)sA + sw) = src[tid];
    }
    __syncthreads();

    const int w = tid >> 5, lane = tid & 31;
    const int mt = w & 1;
    const int ntb = (w >> 1) << 1;
    unsigned sbase = (unsigned)__cvta_generic_to_shared(sA);

    unsigned a0[4], a1[4], a2[4], a3[4];
    #pragma unroll
    for (int kc = 0; kc < 4; kc++) {
        int r = mt * 16 + (lane & 15);
        int cb = ((lane >> 4) << 4) + (kc << 5);
        int boff = r * 128 + cb;
        int bsw = boff ^ (((boff >> 7) & 7) << 4);
        asm("ldmatrix.sync.aligned.m8n8.x4.shared.b16 {%0,%1,%2,%3},[%4];"
            : "=r"(a0[kc]), "=r"(a1[kc]), "=r"(a2[kc]), "=r"(a3[kc])
            : "r"(sbase + bsw));
    }

    const int m = lane & 3;
    float cE0=0.f,cE1=0.f,cE2=0.f,cE3=0.f, cO0=0.f,cO1=0.f,cO2=0.f,cO3=0.f;
    float dE0=0.f,dE1=0.f,dE2=0.f,dE3=0.f, dO0=0.f,dO1=0.f,dO2=0.f,dO3=0.f;

    #pragma unroll
    for (int t = 0; t < 2; t++) {
        int nt = ntb + t;
        const float* wr = W + (nt * 8 + (lane >> 2)) * 64;
        #pragma unroll
        for (int kc = 0; kc < 4; kc++) {
            float2 wA = *(const float2*)(wr + kc * 16 + 2 * m);
            float2 wB = *(const float2*)(wr + kc * 16 + 2 * m + 8);
            float hAx = __half2float(__float2half_rn(wA.x));
            float hAy = __half2float(__float2half_rn(wA.y));
            float hBx = __half2float(__float2half_rn(wB.x));
            float hBy = __half2float(__float2half_rn(wB.y));
            unsigned bh0 = h2pk(hAy, hAx);
            unsigned bh1 = h2pk(hBy, hBx);
            unsigned bl0 = h2pk(wA.y - hAy, wA.x - hAx);
            unsigned bl1 = h2pk(wB.y - hBy, wB.x - hBx);
            if (t == 0) {
                if (kc & 1) {
                    mma_16x8x16(cO0,cO1,cO2,cO3, a0[kc],a1[kc],a2[kc],a3[kc], bh0, bh1);
                    mma_16x8x16(cO0,cO1,cO2,cO3, a0[kc],a1[kc],a2[kc],a3[kc], bl0, bl1);
                } else {
                    mma_16x8x16(cE0,cE1,cE2,cE3, a0[kc],a1[kc],a2[kc],a3[kc], bh0, bh1);
                    mma_16x8x16(cE0,cE1,cE2,cE3, a0[kc],a1[kc],a2[kc],a3[kc], bl0, bl1);
                }
            } else {
                if (kc & 1) {
                    mma_16x8x16(dO0,dO1,dO2,dO3, a0[kc],a1[kc],a2[kc],a3[kc], bh0, bh1);
                    mma_16x8x16(dO0,dO1,dO2,dO3, a0[kc],a1[kc],a2[kc],a3[kc], bl0, bl1);
                } else {
                    mma_16x8x16(dE0,dE1,dE2,dE3, a0[kc],a1[kc],a2[kc],a3[kc], bh0, bh1);
                    mma_16x8x16(dE0,dE1,dE2,dE3, a0[kc],a1[kc],a2[kc],a3[kc], bl0, bl1);
                }
            }
        }
    }

    {
        int r = row0 + mt * 16 + (lane >> 2);
        int e0 = ntb * 8 + 2 * m;
        float2 bb0 = *(const float2*)(bias + e0);
        float2 bb1 = *(const float2*)(bias + e0 + 8);
        *(float2*)(out + (size_t)r * 64 + e0)
            = make_float2(cE0 + cO0 + bb0.x, cE1 + cO1 + bb0.y);
        *(float2*)(out + (size_t)(r + 8) * 64 + e0)
            = make_float2(cE2 + cO2 + bb0.x, cE3 + cO3 + bb0.y);
        *(float2*)(out + (size_t)r * 64 + e0 + 8)
            = make_float2(dE0 + dO0 + bb1.x, dE1 + dO1 + bb1.y);
        *(float2*)(out + (size_t)(r + 8) * 64 + e0 + 8)
            = make_float2(dE2 + dO2 + bb1.x, dE3 + dO3 + bb1.y);
    }
}

// ---------------------------------------------------------------------------
extern "C" void kernel_launch(void* const* d_in, const int* in_sizes, int n_in,
                              void* d_out, int out_size) {
    const float* x    = (const float*)d_in[0];
    const float* phi  = (const float*)d_in[1];
    const float* W    = (const float*)d_in[2];
    const float* bias = (const float*)d_in[3];
    float* out = (float*)d_out;

    cudaFuncSetAttribute(attn_kernel, cudaFuncAttributeMaxDynamicSharedMemorySize,
                         SMEM_BYTES);
    attn_kernel<<<BH * 8, 256, SMEM_BYTES>>>(x, phi);
    epilogue_kernel<<<(BB * SS) / 32, 256>>>(W, bias, out);
}

// round 15
// speedup vs baseline: 1.0703x; 1.0703x over previous
#include <cuda_runtime.h>
#include <cuda_fp16.h>

#define SS   1024
#define BB   8
#define NH   8
#define BH   (BB * NH)          // 64

// Scratch: attention out, fp16, ROW-FEATURE layout [b*1024+s][h*8+d]  (1 MB)
__device__ __half g_aoh[BB * SS * 64];

// attn smem: kh[1024][8] half (16KB), vt[8][1032] half (16.5KB)
#define SM_KH 0
#define SM_VT 16384
#define VT_STRIDE 1032              // word-stride 516 = 4 mod 32: bank-free b-frags
#define SMEM_BYTES (16384 + 8 * VT_STRIDE * 2)   // 32896

__device__ __forceinline__ unsigned h2pk(float hi, float lo) {
    unsigned r; asm("cvt.rn.f16x2.f32 %0,%1,%2;" : "=r"(r) : "f"(hi), "f"(lo)); return r;
}
__device__ __forceinline__ unsigned ex2h2(unsigned x) {
    unsigned r; asm("ex2.approx.f16x2 %0,%1;" : "=r"(r) : "r"(x)); return r;
}
__device__ __forceinline__ unsigned hadd2(unsigned a, unsigned b) {
    unsigned r; asm("add.rn.f16x2 %0,%1,%2;" : "=r"(r) : "r"(a), "r"(b)); return r;
}
__device__ __forceinline__ float2 h2f2(unsigned v) {
    __half2 h = *(__half2*)&v;
    return __half22float2(h);
}
__device__ __forceinline__ void mma_16x8x8(float& c0, float& c1, float& c2, float& c3,
                                           unsigned a0, unsigned a1, unsigned b0) {
    asm("mma.sync.aligned.m16n8k8.row.col.f32.f16.f16.f32 "
        "{%0,%1,%2,%3},{%4,%5},{%6},{%0,%1,%2,%3};"
        : "+f"(c0), "+f"(c1), "+f"(c2), "+f"(c3)
        : "r"(a0), "r"(a1), "r"(b0));
}
__device__ __forceinline__ void mma_16x8x16(float& c0, float& c1, float& c2, float& c3,
                                            unsigned a0, unsigned a1, unsigned a2, unsigned a3,
                                            unsigned b0, unsigned b1) {
    asm("mma.sync.aligned.m16n8k16.row.col.f32.f16.f16.f32 "
        "{%0,%1,%2,%3},{%4,%5,%6,%7},{%8,%9},{%0,%1,%2,%3};"
        : "+f"(c0), "+f"(c1), "+f"(c2), "+f"(c3)
        : "r"(a0), "r"(a1), "r"(a2), "r"(a3), "r"(b0), "r"(b1));
}

// QK issue for one tile into score regs S (4 groups x 4)
#define QK_ISSUE(S, QA0, QA1, B0, B1, B2, B3)  do {                            \
    S##00=0.f;S##01=0.f;S##02=0.f;S##03=0.f;                                   \
    S##10=0.f;S##11=0.f;S##12=0.f;S##13=0.f;                                   \
    S##20=0.f;S##21=0.f;S##22=0.f;S##23=0.f;                                   \
    S##30=0.f;S##31=0.f;S##32=0.f;S##33=0.f;                                   \
    mma_16x8x8(S##00,S##01,S##02,S##03, QA0,QA1, B0);                          \
    mma_16x8x8(S##10,S##11,S##12,S##13, QA0,QA1, B1);                          \
    mma_16x8x8(S##20,S##21,S##22,S##23, QA0,QA1, B2);                          \
    mma_16x8x8(S##30,S##31,S##32,S##33, QA0,QA1, B3);                          \
} while (0)

// Consume scores S: ex2 -> L accumulate -> 2 PV mmas into OX/OY quads
#define CONSUME(S, L0, L1, OX0,OX1,OX2,OX3, OY0,OY1,OY2,OY3, VB0,VB1,VB2,VB3) do { \
    unsigned a00 = ex2h2(h2pk(S##01, S##00));                                  \
    unsigned a01 = ex2h2(h2pk(S##03, S##02));                                  \
    unsigned a10 = ex2h2(h2pk(S##11, S##10));                                  \
    unsigned a11 = ex2h2(h2pk(S##13, S##12));                                  \
    unsigned a20 = ex2h2(h2pk(S##21, S##20));                                  \
    unsigned a21 = ex2h2(h2pk(S##23, S##22));                                  \
    unsigned a30 = ex2h2(h2pk(S##31, S##30));                                  \
    unsigned a31 = ex2h2(h2pk(S##33, S##32));                                  \
    unsigned T0 = hadd2(hadd2(a00, a10), hadd2(a20, a30));                     \
    unsigned T1 = hadd2(hadd2(a01, a11), hadd2(a21, a31));                     \
    float2 f0 = h2f2(T0);                                                      \
    float2 f1 = h2f2(T1);                                                      \
    L0 += f0.x + f0.y;                                                         \
    L1 += f1.x + f1.y;                                                         \
    mma_16x8x16(OX0,OX1,OX2,OX3, a00, a01, a10, a11, VB0, VB1);                \
    mma_16x8x16(OY0,OY1,OY2,OY3, a20, a21, a30, a31, VB2, VB3);                \
} while (0)

// ---------------------------------------------------------------------------
// Fused qlayer + flash-attention via mma.sync, CROSS-ITERATION pipelined:
// QK(c+32) for both row-tiles is issued a full iteration before its scores
// are consumed -> HMMA result latency fully hidden in steady state.
// Grid 256 = 64 heads x 4 (2 blocks/SM, ONE wave); 8 warps; each warp owns
// two 16-row tiles (r0, r0+128) sharing the key/value b-fragments.
// ---------------------------------------------------------------------------
__global__ __launch_bounds__(256, 2) void attn_kernel(const float* __restrict__ x,
                                                      const float* __restrict__ phi) {
    extern __shared__ char dynsmem[];
    __half*  kh = (__half*)(dynsmem + SM_KH);       // [j][8] row-major fp16
    __half*  vt = (__half*)(dynsmem + SM_VT);       // [d][VT_STRIDE] fp16
    const unsigned* khw = (const unsigned*)kh;      // half2 words: [j*4 + p]
    const unsigned* vtw = (const unsigned*)vt;      // [d*516 + j/2]

    const int blk = blockIdx.x;
    const int bh = blk >> 2;
    const int b = bh >> 3, h = bh & 7;
    const int tid = threadIdx.x;

    float ph0 = phi[0], ph1 = phi[1], ph2 = phi[2], ph3 = phi[3];
    float ph4 = phi[4], ph5 = phi[5], ph6 = phi[6], ph7 = phi[7];

    // ---- prologue: qlayer (prefix products of cos) -> kh and vt ----
    #pragma unroll
    for (int it = 0; it < 4; it++) {
        int s = tid + it * 256;
        const float4* xp = (const float4*)(x + ((size_t)((b << 10) + s) << 6) + (h << 3));
        float4 xa = xp[0];
        float4 xb = xp[1];
        float k0 = __cosf(xa.x + ph0);
        float c1 = __cosf(xa.y + ph1);
        float c2 = __cosf(xa.z + ph2);
        float c3 = __cosf(xa.w + ph3);
        float c4 = __cosf(xb.x + ph4);
        float c5 = __cosf(xb.y + ph5);
        float c6 = __cosf(xb.z + ph6);
        float c7 = __cosf(xb.w + ph7);
        float kv1 = k0 * c1;
        float kv2 = kv1 * c2;
        float kv3 = kv2 * c3;
        float kv4 = kv3 * c4;
        float kv5 = kv4 * c5;
        float kv6 = kv5 * c6;
        float kv7 = kv6 * c7;
        float t = c1 * c2;
        t *= c3; t *= c4; t *= c5; t *= c6; t *= c7;

        unsigned w0 = h2pk(kv1, t);
        unsigned w1 = h2pk(kv3, kv2);
        unsigned w2 = h2pk(kv5, kv4);
        unsigned w3 = h2pk(kv7, kv6);
        ((uint4*)kh)[s] = make_uint4(w0, w1, w2, w3);

        __half2 p0 = *(__half2*)&w0, p1 = *(__half2*)&w1;
        __half2 p2 = *(__half2*)&w2, p3 = *(__half2*)&w3;
        vt[0 * VT_STRIDE + s] = p0.x;
        vt[1 * VT_STRIDE + s] = p0.y;
        vt[2 * VT_STRIDE + s] = p1.x;
        vt[3 * VT_STRIDE + s] = p1.y;
        vt[4 * VT_STRIDE + s] = p2.x;
        vt[5 * VT_STRIDE + s] = p2.y;
        vt[6 * VT_STRIDE + s] = p3.x;
        vt[7 * VT_STRIDE + s] = p3.y;
    }
    __syncthreads();

    // ---- per-warp Q fragments for BOTH tiles ----
    const int wid = tid >> 5, lane = tid & 31;
    const int r0A = ((blk & 3) << 8) + (wid << 4);
    const int r0B = r0A + 128;
    const int qr = lane >> 2, qm = lane & 3;
    const float SC = 0.35355339059327373f * 1.4426950408889634f;

    unsigned qA0, qA1, qB0, qB1;
    {
        float2 f;
        f = h2f2(khw[(r0A + qr) * 4 + qm]);      qA0 = h2pk(f.y * SC, f.x * SC);
        f = h2f2(khw[(r0A + qr + 8) * 4 + qm]);  qA1 = h2pk(f.y * SC, f.x * SC);
        f = h2f2(khw[(r0B + qr) * 4 + qm]);      qB0 = h2pk(f.y * SC, f.x * SC);
        f = h2f2(khw[(r0B + qr + 8) * 4 + qm]);  qB1 = h2pk(f.y * SC, f.x * SC);
    }

    // accumulators
    float oAX0=0.f,oAX1=0.f,oAX2=0.f,oAX3=0.f, oAY0=0.f,oAY1=0.f,oAY2=0.f,oAY3=0.f;
    float oBX0=0.f,oBX1=0.f,oBX2=0.f,oBX3=0.f, oBY0=0.f,oBY1=0.f,oBY2=0.f,oBY3=0.f;
    float lA0=0.f, lA1=0.f, lB0=0.f, lB1=0.f;

    const int vbase = (lane >> 2) * (VT_STRIDE / 2) + (lane & 3);

    // scores (single buffer per tile: reissued only after consumption)
    float sA00,sA01,sA02,sA03, sA10,sA11,sA12,sA13;
    float sA20,sA21,sA22,sA23, sA30,sA31,sA32,sA33;
    float sB00,sB01,sB02,sB03, sB10,sB11,sB12,sB13;
    float sB20,sB21,sB22,sB23, sB30,sB31,sB32,sB33;

    // current b-frags (keys + values) for chunk c
    unsigned cb0 = khw[0 * 4 + lane];
    unsigned cb1 = khw[8 * 4 + lane];
    unsigned cb2 = khw[16 * 4 + lane];
    unsigned cb3 = khw[24 * 4 + lane];
    unsigned cv0 = vtw[vbase];
    unsigned cv1 = vtw[vbase + 4];
    unsigned cv2 = vtw[vbase + 8];
    unsigned cv3 = vtw[vbase + 12];

    // pipeline prologue: issue QK for chunk 0, both tiles
    QK_ISSUE(sA, qA0, qA1, cb0, cb1, cb2, cb3);
    QK_ISSUE(sB, qB0, qB1, cb0, cb1, cb2, cb3);

    for (int c = 0; c < SS - 32; c += 32) {
        // prefetch next chunk's b-frags
        int n = c + 32;
        unsigned nb0 = khw[(n +  0) * 4 + lane];
        unsigned nb1 = khw[(n +  8) * 4 + lane];
        unsigned nb2 = khw[(n + 16) * 4 + lane];
        unsigned nb3 = khw[(n + 24) * 4 + lane];
        unsigned nv0 = vtw[vbase + (n >> 1)];
        unsigned nv1 = vtw[vbase + (n >> 1) + 4];
        unsigned nv2 = vtw[vbase + (n >> 1) + 8];
        unsigned nv3 = vtw[vbase + (n >> 1) + 12];

        // consume A(c) — scores issued a full iteration ago
        CONSUME(sA, lA0, lA1, oAX0,oAX1,oAX2,oAX3, oAY0,oAY1,oAY2,oAY3,
                cv0, cv1, cv2, cv3);
        // reissue A for next chunk
        QK_ISSUE(sA, qA0, qA1, nb0, nb1, nb2, nb3);

        // consume B(c)
        CONSUME(sB, lB0, lB1, oBX0,oBX1,oBX2,oBX3, oBY0,oBY1,oBY2,oBY3,
                cv0, cv1, cv2, cv3);
        // reissue B for next chunk
        QK_ISSUE(sB, qB0, qB1, nb0, nb1, nb2, nb3);

        cv0 = nv0; cv1 = nv1; cv2 = nv2; cv3 = nv3;
        cb0 = nb0; cb1 = nb1; cb2 = nb2; cb3 = nb3;
    }

    // pipeline epilogue: consume final chunk
    CONSUME(sA, lA0, lA1, oAX0,oAX1,oAX2,oAX3, oAY0,oAY1,oAY2,oAY3,
            cv0, cv1, cv2, cv3);
    CONSUME(sB, lB0, lB1, oBX0,oBX1,oBX2,oBX3, oBY0,oBY1,oBY2,oBY3,
            cv0, cv1, cv2, cv3);

    // ---- reduce L across quads, write both tiles ----
    lA0 += __shfl_xor_sync(0xffffffffu, lA0, 1);
    lA0 += __shfl_xor_sync(0xffffffffu, lA0, 2);
    lA1 += __shfl_xor_sync(0xffffffffu, lA1, 1);
    lA1 += __shfl_xor_sync(0xffffffffu, lA1, 2);
    lB0 += __shfl_xor_sync(0xffffffffu, lB0, 1);
    lB0 += __shfl_xor_sync(0xffffffffu, lB0, 2);
    lB1 += __shfl_xor_sync(0xffffffffu, lB1, 1);
    lB1 += __shfl_xor_sync(0xffffffffu, lB1, 2);

    unsigned* aoh = (unsigned*)g_aoh;
    {
        float inv0 = 1.f / lA0, inv1 = 1.f / lA1;
        float o0 = oAX0 + oAY0, o1 = oAX1 + oAY1, o2 = oAX2 + oAY2, o3 = oAX3 + oAY3;
        int roww = (((b << 10) + r0A + qr) << 5) + (h << 2) + qm;
        aoh[roww]       = h2pk(o1 * inv0, o0 * inv0);
        aoh[roww + 256] = h2pk(o3 * inv1, o2 * inv1);
    }
    {
        float inv0 = 1.f / lB0, inv1 = 1.f / lB1;
        float o0 = oBX0 + oBY0, o1 = oBX1 + oBY1, o2 = oBX2 + oBY2, o3 = oBX3 + oBY3;
        int roww = (((b << 10) + r0B + qr) << 5) + (h << 2) + qm;
        aoh[roww]       = h2pk(o1 * inv0, o0 * inv0);
        aoh[roww + 256] = h2pk(o3 * inv1, o2 * inv1);
    }
}

// ---------------------------------------------------------------------------
// Tensor-core epilogue (unchanged): out = ao @ W^T + bias.
// ---------------------------------------------------------------------------
__global__ __launch_bounds__(256) void epilogue_kernel(const float* __restrict__ W,
                                                       const float* __restrict__ bias,
                                                       float* __restrict__ out) {
    __shared__ __align__(16) __half sA[32 * 64];    // 4 KB

    const int tid = threadIdx.x;
    const int row0 = blockIdx.x * 32;

    {
        const uint4* src = (const uint4*)((const __half*)g_aoh + (size_t)row0 * 64);
        int off = tid * 16;
        int sw = off ^ (((off >> 7) & 7) << 4);
        *(uint4*)((char*)sA + sw) = src[tid];
    }
    __syncthreads();

    const int w = tid >> 5, lane = tid & 31;
    const int mt = w & 1;
    const int ntb = (w >> 1) << 1;
    unsigned sbase = (unsigned)__cvta_generic_to_shared(sA);

    unsigned a0[4], a1[4], a2[4], a3[4];
    #pragma unroll
    for (int kc = 0; kc < 4; kc++) {
        int r = mt * 16 + (lane & 15);
        int cb = ((lane >> 4) << 4) + (kc << 5);
        int boff = r * 128 + cb;
        int bsw = boff ^ (((boff >> 7) & 7) << 4);
        asm("ldmatrix.sync.aligned.m8n8.x4.shared.b16 {%0,%1,%2,%3},[%4];"
            : "=r"(a0[kc]), "=r"(a1[kc]), "=r"(a2[kc]), "=r"(a3[kc])
            : "r"(sbase + bsw));
    }

    const int m = lane & 3;
    float cE0=0.f,cE1=0.f,cE2=0.f,cE3=0.f, cO0=0.f,cO1=0.f,cO2=0.f,cO3=0.f;
    float dE0=0.f,dE1=0.f,dE2=0.f,dE3=0.f, dO0=0.f,dO1=0.f,dO2=0.f,dO3=0.f;

    #pragma unroll
    for (int t = 0; t < 2; t++) {
        int nt = ntb + t;
        const float* wr = W + (nt * 8 + (lane >> 2)) * 64;
        #pragma unroll
        for (int kc = 0; kc < 4; kc++) {
            float2 wA = *(const float2*)(wr + kc * 16 + 2 * m);
            float2 wB = *(const float2*)(wr + kc * 16 + 2 * m + 8);
            float hAx = __half2float(__float2half_rn(wA.x));
            float hAy = __half2float(__float2half_rn(wA.y));
            float hBx = __half2float(__float2half_rn(wB.x));
            float hBy = __half2float(__float2half_rn(wB.y));
            unsigned bh0 = h2pk(hAy, hAx);
            unsigned bh1 = h2pk(hBy, hBx);
            unsigned bl0 = h2pk(wA.y - hAy, wA.x - hAx);
            unsigned bl1 = h2pk(wB.y - hBy, wB.x - hBx);
            if (t == 0) {
                if (kc & 1) {
                    mma_16x8x16(cO0,cO1,cO2,cO3, a0[kc],a1[kc],a2[kc],a3[kc], bh0, bh1);
                    mma_16x8x16(cO0,cO1,cO2,cO3, a0[kc],a1[kc],a2[kc],a3[kc], bl0, bl1);
                } else {
                    mma_16x8x16(cE0,cE1,cE2,cE3, a0[kc],a1[kc],a2[kc],a3[kc], bh0, bh1);
                    mma_16x8x16(cE0,cE1,cE2,cE3, a0[kc],a1[kc],a2[kc],a3[kc], bl0, bl1);
                }
            } else {
                if (kc & 1) {
                    mma_16x8x16(dO0,dO1,dO2,dO3, a0[kc],a1[kc],a2[kc],a3[kc], bh0, bh1);
                    mma_16x8x16(dO0,dO1,dO2,dO3, a0[kc],a1[kc],a2[kc],a3[kc], bl0, bl1);
                } else {
                    mma_16x8x16(dE0,dE1,dE2,dE3, a0[kc],a1[kc],a2[kc],a3[kc], bh0, bh1);
                    mma_16x8x16(dE0,dE1,dE2,dE3, a0[kc],a1[kc],a2[kc],a3[kc], bl0, bl1);
                }
            }
        }
    }

    {
        int r = row0 + mt * 16 + (lane >> 2);
        int e0 = ntb * 8 + 2 * m;
        float2 bb0 = *(const float2*)(bias + e0);
        float2 bb1 = *(const float2*)(bias + e0 + 8);
        *(float2*)(out + (size_t)r * 64 + e0)
            = make_float2(cE0 + cO0 + bb0.x, cE1 + cO1 + bb0.y);
        *(float2*)(out + (size_t)(r + 8) * 64 + e0)
            = make_float2(cE2 + cO2 + bb0.x, cE3 + cO3 + bb0.y);
        *(float2*)(out + (size_t)r * 64 + e0 + 8)
            = make_float2(dE0 + dO0 + bb1.x, dE1 + dO1 + bb1.y);
        *(float2*)(out + (size_t)(r + 8) * 64 + e0 + 8)
            = make_float2(dE2 + dO2 + bb1.x, dE3 + dO3 + bb1.y);
    }
}

// ---------------------------------------------------------------------------
extern "C" void kernel_launch(void* const* d_in, const int* in_sizes, int n_in,
                              void* d_out, int out_size) {
    const float* x    = (const float*)d_in[0];
    const float* phi  = (const float*)d_in[1];
    const float* W    = (const float*)d_in[2];
    const float* bias = (const float*)d_in[3];
    float* out = (float*)d_out;

    cudaFuncSetAttribute(attn_kernel, cudaFuncAttributeMaxDynamicSharedMemorySize,
                         SMEM_BYTES);
    attn_kernel<<<BH * 4, 256, SMEM_BYTES>>>(x, phi);
    epilogue_kernel<<<(BB * SS) / 32, 256>>>(W, bias, out);
}